// round 10
// baseline (speedup 1.0000x reference)
#include <cuda_runtime.h>
#include <math.h>
#include <stdint.h>

#define N_NODES 20000
#define N_EDGES 320000
#define T_STEPS 16
#define HG 64
#define HT 128
#define G3 384
#define NT (N_NODES * T_STEPS)
#define LN_EPS 1e-5f

// ===================== scratch (static device globals) =======================
__device__ int   g_cnt[N_NODES];
__device__ int   g_fill[N_NODES];
__device__ int   g_rowptr[N_NODES + 1];
__device__ int   g_col[N_EDGES];
__device__ float g_h0_all[NT * HG];
__device__ float g_ins_all[NT * (2 * HG)];
__device__ float g_H_all[NT * HG];
__device__ float g_hid[N_NODES * HT];

// pre-split packed-bf16 weights, fragment-contiguous: P[(rb*K2 + c)*8 + (row&7)]
__device__ uint32_t g_ws1h[8  * 64 * 8], g_ws1l[8  * 64 * 8];   // ws1: 64 rows, K2=64
__device__ uint32_t g_wgh[48 * 96 * 8],  g_wgl[48 * 96 * 8];    // [Wih|Whh]: 384 rows, K2=96

__device__ __forceinline__ float warp_sum(float v) {
#pragma unroll
    for (int o = 16; o; o >>= 1) v += __shfl_xor_sync(0xFFFFFFFFu, v, o);
    return v;
}

// bf16x2 split: returns packed hi pair, writes packed lo pair (lo = v - hi)
__device__ __forceinline__ uint32_t pack_split(float x0, float x1, uint32_t& lo) {
    uint32_t hi;
    asm("cvt.rn.bf16x2.f32 %0, %1, %2;" : "=r"(hi) : "f"(x1), "f"(x0));
    float h0 = __uint_as_float(hi << 16);
    float h1 = __uint_as_float(hi & 0xFFFF0000u);
    float l0 = x0 - h0, l1 = x1 - h1;
    asm("cvt.rn.bf16x2.f32 %0, %1, %2;" : "=r"(lo) : "f"(l1), "f"(l0));
    return hi;
}

// m16n8k16 bf16 MMA (sm_80+ generic PTX)
__device__ __forceinline__ void mma16(float* d, const uint32_t* a, uint32_t b0, uint32_t b1) {
    asm volatile(
        "mma.sync.aligned.m16n8k16.row.col.f32.bf16.bf16.f32 "
        "{%0,%1,%2,%3}, {%4,%5,%6,%7}, {%8,%9}, {%0,%1,%2,%3};"
        : "+f"(d[0]), "+f"(d[1]), "+f"(d[2]), "+f"(d[3])
        : "r"(a[0]), "r"(a[1]), "r"(a[2]), "r"(a[3]), "r"(b0), "r"(b1));
}

// ------------------------- CSR build -----------------------------------------
__global__ void k_hist(const int* __restrict__ ei) {
    int e = blockIdx.x * blockDim.x + threadIdx.x;
    if (e < N_EDGES) atomicAdd(&g_cnt[ei[N_EDGES + e]], 1);
}

__global__ void k_scan() {
    __shared__ int sh[1024];
    __shared__ int base;
    int tid = threadIdx.x;
    if (tid == 0) { base = 0; g_rowptr[0] = 0; }
    __syncthreads();
    for (int start = 0; start < N_NODES; start += 1024) {
        int i = start + tid;
        int v = (i < N_NODES) ? g_cnt[i] : 0;
        sh[tid] = v;
        __syncthreads();
        for (int off = 1; off < 1024; off <<= 1) {
            int t = (tid >= off) ? sh[tid - off] : 0;
            __syncthreads();
            sh[tid] += t;
            __syncthreads();
        }
        if (i < N_NODES) g_rowptr[i + 1] = base + sh[tid];
        __syncthreads();
        if (tid == 1023) base += sh[1023];
        __syncthreads();
    }
    for (int i = tid; i < N_NODES; i += 1024) { g_cnt[i] = 0; g_fill[i] = 0; }
}

__global__ void k_scatter(const int* __restrict__ ei) {
    int e = blockIdx.x * blockDim.x + threadIdx.x;
    if (e >= N_EDGES) return;
    int d = ei[N_EDGES + e];
    int p = atomicAdd(&g_fill[d], 1);
    g_col[g_rowptr[d] + p] = ei[e];
}

// ------------------- weight pre-split kernels ---------------------------------
// Destinations referenced in DEVICE code only (GB300/ATS host-shadow trap).
__global__ void k_prep_ws1(const float* __restrict__ Wl1, const float* __restrict__ Wr1) {
    int idx = blockIdx.x * blockDim.x + threadIdx.x;   // 64 * 64
    if (idx >= 64 * 64) return;
    int m = idx >> 6, c = idx & 63;
    int k0 = 2 * c;
    float v0 = (k0 < 64) ? Wl1[k0 * 64 + m] : Wr1[(k0 - 64) * 64 + m];
    float v1 = (k0 + 1 < 64) ? Wl1[(k0 + 1) * 64 + m] : Wr1[(k0 - 63) * 64 + m];
    uint32_t lo, hi = pack_split(v0, v1, lo);
    int o = ((m >> 3) * 64 + c) * 8 + (m & 7);
    g_ws1h[o] = hi; g_ws1l[o] = lo;
}

// combined [Wih (K 0..63) | Whh (K 64..191)], 384 rows, K=192 (K2=96)
__global__ void k_prep_wg(const float* __restrict__ Wih, const float* __restrict__ Whh) {
    int idx = blockIdx.x * blockDim.x + threadIdx.x;   // 384 * 96
    if (idx >= G3 * 96) return;
    int row = idx / 96, c = idx % 96;
    int k0 = 2 * c, k1 = 2 * c + 1;                    // pairs never straddle k=64
    float v0 = (k0 < 64) ? Wih[row * 64 + k0] : Whh[row * 128 + k0 - 64];
    float v1 = (k1 < 64) ? Wih[row * 64 + k1] : Whh[row * 128 + k1 - 64];
    uint32_t lo, hi = pack_split(v0, v1, lo);
    int o = ((row >> 3) * 96 + c) * 8 + (row & 7);
    g_wgh[o] = hi; g_wgl[o] = lo;
}

__global__ void k_zero_hid() {
    int idx = blockIdx.x * blockDim.x + threadIdx.x;
    if (idx < N_NODES * HT) g_hid[idx] = 0.f;
}

// ------------------- layer 0 (batched): agg + SAGE + LN + relu ----------------
__global__ void k_stack0_all(const float* __restrict__ x_seq,
                             const float* __restrict__ Wl, const float* __restrict__ Wr,
                             const float* __restrict__ b0,
                             const float* __restrict__ g, const float* __restrict__ beta) {
    int t = blockIdx.y;
    int n = blockIdx.x * 8 + (threadIdx.x >> 5);
    int lane = threadIdx.x & 31;
    if (n >= N_NODES) return;
    const float* xt = x_seq + t * N_NODES;
    int beg = g_rowptr[n], end = g_rowptr[n + 1];
    float acc = 0.f;
    for (int i = beg + lane; i < end; i += 32) acc += xt[g_col[i]];
    acc = warp_sum(acc);
    float deg = fmaxf((float)(end - beg), 1.f);
    float agg = acc / deg;
    float xv = xt[n];
    float v0 = agg * Wl[lane]      + xv * Wr[lane]      + b0[lane];
    float v1 = agg * Wl[lane + 32] + xv * Wr[lane + 32] + b0[lane + 32];
    float mu = warp_sum(v0 + v1) * (1.f / 64.f);
    float d0 = v0 - mu, d1 = v1 - mu;
    float var = warp_sum(d0 * d0 + d1 * d1) * (1.f / 64.f);
    float inv = rsqrtf(var + LN_EPS);
    float h0a = fmaxf(d0 * inv * g[lane]      + beta[lane], 0.f);
    float h0b = fmaxf(d1 * inv * g[lane + 32] + beta[lane + 32], 0.f);
    size_t row = (size_t)t * N_NODES + n;
    g_h0_all[row * HG + lane]      = h0a;
    g_h0_all[row * HG + lane + 32] = h0b;
    g_ins_all[row * 128 + 64 + lane]      = h0a;
    g_ins_all[row * 128 + 64 + lane + 32] = h0b;
}

// ------------------- layer 1 aggregate (batched, 2-way unrolled) --------------
__global__ void k_agg1_all() {
    int t = blockIdx.y;
    int n = blockIdx.x * 8 + (threadIdx.x >> 5);
    int lane = threadIdx.x & 31;
    if (n >= N_NODES) return;
    const float* h0t = g_h0_all + (size_t)t * N_NODES * HG;
    int beg = g_rowptr[n], end = g_rowptr[n + 1];
    float a0 = 0.f, a1 = 0.f, c0 = 0.f, c1 = 0.f;
    int i = beg;
    for (; i + 1 < end; i += 2) {
        int s0 = g_col[i], s1 = g_col[i + 1];
        a0 += h0t[s0 * HG + lane];
        a1 += h0t[s0 * HG + lane + 32];
        c0 += h0t[s1 * HG + lane];
        c1 += h0t[s1 * HG + lane + 32];
    }
    if (i < end) {
        int s = g_col[i];
        a0 += h0t[s * HG + lane];
        a1 += h0t[s * HG + lane + 32];
    }
    a0 += c0; a1 += c1;
    float inv = 1.f / fmaxf((float)(end - beg), 1.f);
    size_t row = (size_t)t * N_NODES + n;
    g_ins_all[row * 128 + lane]      = a0 * inv;
    g_ins_all[row * 128 + lane + 32] = a1 * inv;
}

// ===================== sage1 bf16x3 GEMM (MODE 0 of old scheme) ================
// S = ins_all(NTx128) @ ws1^T(64x128); epilogue: +b1, LN, relu -> g_H_all
__global__ void __launch_bounds__(256)
k_sage(const float* __restrict__ bias, const float* __restrict__ p0,
       const float* __restrict__ p1) {
    constexpr int K2  = 64;
    constexpr int LDK = K2 + 4;
    constexpr int BM  = 128;

    extern __shared__ uint32_t smu[];
    uint32_t* Ah = smu;
    uint32_t* Al = Ah + BM * LDK;

    int tid = threadIdx.x;
    int rowBase = blockIdx.y * BM;

    for (int idx = tid; idx < BM * 32; idx += 256) {
        int r = idx >> 5, c4 = idx & 31;
        float4 v = *(const float4*)(g_ins_all + ((size_t)rowBase + r) * 128 + c4 * 4);
        uint32_t lo0, lo1;
        uint32_t hi0 = pack_split(v.x, v.y, lo0);
        uint32_t hi1 = pack_split(v.z, v.w, lo1);
        int j = r * LDK + c4 * 2;
        Ah[j] = hi0; Ah[j + 1] = hi1;
        Al[j] = lo0; Al[j + 1] = lo1;
    }
    __syncthreads();

    int warp = tid >> 5, lane = tid & 31;
    int wm = warp >> 1, wn = warp & 1;           // 4 x 2 warps, WM=32, WN=32
    int g = lane >> 2, tg = lane & 3;
    int m0 = wm * 32, n0 = wn * 32;

    float acc[2][4][4] = {};
#pragma unroll
    for (int kk = 0; kk < K2; kk += 8) {
        uint32_t ah[2][4], al[2][4];
#pragma unroll
        for (int mf = 0; mf < 2; mf++) {
            int base = (m0 + 16 * mf + g) * LDK + kk + tg;
            ah[mf][0] = Ah[base];               al[mf][0] = Al[base];
            ah[mf][1] = Ah[base + 8 * LDK];     al[mf][1] = Al[base + 8 * LDK];
            ah[mf][2] = Ah[base + 4];           al[mf][2] = Al[base + 4];
            ah[mf][3] = Ah[base + 8 * LDK + 4]; al[mf][3] = Al[base + 8 * LDK + 4];
        }
#pragma unroll
        for (int nf = 0; nf < 4; nf++) {
            int nrow = n0 + 8 * nf;
            int fo = ((nrow >> 3) * K2 + kk + tg) * 8 + g;
            uint32_t bh0 = g_ws1h[fo], bh1 = g_ws1h[fo + 32];
            uint32_t bl0 = g_ws1l[fo], bl1 = g_ws1l[fo + 32];
#pragma unroll
            for (int mf = 0; mf < 2; mf++) {
                mma16(acc[mf][nf], al[mf], bh0, bh1);
                mma16(acc[mf][nf], ah[mf], bl0, bl1);
                mma16(acc[mf][nf], ah[mf], bh0, bh1);
            }
        }
    }

    __syncthreads();
    float* S = (float*)smu;                      // 128 x 68
#pragma unroll
    for (int mf = 0; mf < 2; mf++)
#pragma unroll
        for (int nf = 0; nf < 4; nf++) {
            int r = m0 + 16 * mf + g;
            int c = n0 + 8 * nf + 2 * tg;
            S[r * 68 + c]           = acc[mf][nf][0] + bias[c];
            S[r * 68 + c + 1]       = acc[mf][nf][1] + bias[c + 1];
            S[(r + 8) * 68 + c]     = acc[mf][nf][2] + bias[c];
            S[(r + 8) * 68 + c + 1] = acc[mf][nf][3] + bias[c + 1];
        }
    __syncthreads();
#pragma unroll
    for (int i = 0; i < 16; i++) {
        int r = warp * 16 + i;
        float v0 = S[r * 68 + lane];
        float v1 = S[r * 68 + lane + 32];
        float mu = warp_sum(v0 + v1) * (1.f / 64.f);
        float d0 = v0 - mu, d1 = v1 - mu;
        float var = warp_sum(d0 * d0 + d1 * d1) * (1.f / 64.f);
        float inv = rsqrtf(var + LN_EPS);
        size_t rowg = (size_t)rowBase + r;
        g_H_all[rowg * HG + lane]      = fmaxf(d0 * inv * p0[lane]      + p1[lane], 0.f);
        g_H_all[rowg * HG + lane + 32] = fmaxf(d1 * inv * p0[lane + 32] + p1[lane + 32], 0.f);
    }
}

// ===================== fused GRU step: gi GEMM + gh GEMM + gates ===============
// A = [H_t (K 0..63) | hid (K 64..191)], B = combined [Wih|Whh] (384 x 192).
// n-gate uses split accumulators: acc[2] over k<64 (inn), acc[3] over k>=64 (hn).
// h' = (1-z)*tanh(inn+bih_n + r*(hn+bhh_n)) + z*h
__global__ void __launch_bounds__(256)
k_gru(const float* __restrict__ bih, const float* __restrict__ bhh, int t) {
    constexpr int K2  = 96;
    constexpr int LDK = K2 + 4;                 // 100; %32==4 -> conflict-free
    constexpr int BM  = 128;

    extern __shared__ uint32_t smu[];
    uint32_t* Ah = smu;
    uint32_t* Al = Ah + BM * LDK;

    int tid = threadIdx.x;
    int rowBase = blockIdx.y * BM;
    int colBase = blockIdx.x * 64;              // 0 or 64

    const float* Ht = g_H_all + (size_t)t * N_NODES * HG;

    // ---- stage A tile: [H_t row (16 float4) | hid row (32 float4)] ----
    for (int idx = tid; idx < BM * 48; idx += 256) {
        int r = idx / 48, q = idx % 48;
        int node = rowBase + r;
        float4 v = make_float4(0.f, 0.f, 0.f, 0.f);
        if (node < N_NODES) {
            if (q < 16) v = *(const float4*)(Ht + (size_t)node * HG + q * 4);
            else        v = *(const float4*)(g_hid + (size_t)node * HT + (q - 16) * 4);
        }
        uint32_t lo0, lo1;
        uint32_t hi0 = pack_split(v.x, v.y, lo0);
        uint32_t hi1 = pack_split(v.z, v.w, lo1);
        int j = r * LDK + q * 2;
        Ah[j] = hi0; Ah[j + 1] = hi1;
        Al[j] = lo0; Al[j + 1] = lo1;
    }
    __syncthreads();

    int warp = tid >> 5, lane = tid & 31;
    int wm = warp >> 2, wn = warp & 3;          // 2 x 4 warps, WM=64, WN=16
    int g = lane >> 2, tg = lane & 3;
    int m0 = wm * 64, n0 = wn * 16;

    float acc[4][4][2][4] = {};                 // [r,z,n_i,n_h][MF][NF][4]

#pragma unroll
    for (int kk = 0; kk < K2; kk += 8) {
        uint32_t ah[4][4], al[4][4];
#pragma unroll
        for (int mf = 0; mf < 4; mf++) {
            int base = (m0 + 16 * mf + g) * LDK + kk + tg;
            ah[mf][0] = Ah[base];               al[mf][0] = Al[base];
            ah[mf][1] = Ah[base + 8 * LDK];     al[mf][1] = Al[base + 8 * LDK];
            ah[mf][2] = Ah[base + 4];           al[mf][2] = Al[base + 4];
            ah[mf][3] = Ah[base + 8 * LDK + 4]; al[mf][3] = Al[base + 8 * LDK + 4];
        }
#pragma unroll
        for (int gt = 0; gt < 3; gt++) {
            int at = (gt < 2) ? gt : ((kk < 32) ? 2 : 3);   // n-gate k-split
#pragma unroll
            for (int nf = 0; nf < 2; nf++) {
                int nrow = gt * HT + colBase + n0 + 8 * nf;
                int fo = ((nrow >> 3) * K2 + kk + tg) * 8 + g;
                uint32_t bh0 = g_wgh[fo], bh1 = g_wgh[fo + 32];
                uint32_t bl0 = g_wgl[fo], bl1 = g_wgl[fo + 32];
#pragma unroll
                for (int mf = 0; mf < 4; mf++) {
                    mma16(acc[at][mf][nf], al[mf], bh0, bh1);
                    mma16(acc[at][mf][nf], ah[mf], bl0, bl1);
                    mma16(acc[at][mf][nf], ah[mf], bh0, bh1);
                }
            }
        }
    }

    // ---- fused gates epilogue ----
#pragma unroll
    for (int mf = 0; mf < 4; mf++)
#pragma unroll
        for (int nf = 0; nf < 2; nf++)
#pragma unroll
            for (int half = 0; half < 2; half++) {
                int node = rowBase + m0 + 16 * mf + g + half * 8;
                if (node >= N_NODES) continue;
                int c = colBase + n0 + 8 * nf + 2 * tg;
                int h2 = half * 2;
                float r0 = 1.f / (1.f + __expf(-(acc[0][mf][nf][h2]     + bih[c]     + bhh[c])));
                float r1 = 1.f / (1.f + __expf(-(acc[0][mf][nf][h2 + 1] + bih[c + 1] + bhh[c + 1])));
                float z0 = 1.f / (1.f + __expf(-(acc[1][mf][nf][h2]     + bih[128 + c]     + bhh[128 + c])));
                float z1 = 1.f / (1.f + __expf(-(acc[1][mf][nf][h2 + 1] + bih[128 + c + 1] + bhh[128 + c + 1])));
                float in0 = acc[2][mf][nf][h2]     + bih[256 + c];
                float in1 = acc[2][mf][nf][h2 + 1] + bih[256 + c + 1];
                float hn0 = acc[3][mf][nf][h2]     + bhh[256 + c];
                float hn1 = acc[3][mf][nf][h2 + 1] + bhh[256 + c + 1];
                float n0v = tanhf(in0 + r0 * hn0);
                float n1v = tanhf(in1 + r1 * hn1);
                float* hid = g_hid + (size_t)node * HT + c;
                float2 h = *(float2*)hid;
                h.x = (1.f - z0) * n0v + z0 * h.x;
                h.y = (1.f - z1) * n1v + z1 * h.y;
                *(float2*)hid = h;
            }
}

// ------------------- output head -----------------------------------------------
__global__ void k_head(const float* __restrict__ W, const float* __restrict__ b,
                       float* __restrict__ y) {
    int warp = (blockIdx.x * blockDim.x + threadIdx.x) >> 5;
    int lane = threadIdx.x & 31;
    if (warp >= N_NODES) return;
    float acc = 0.f;
#pragma unroll
    for (int i = 0; i < 4; i++) {
        int j = lane + 32 * i;
        acc += g_hid[warp * HT + j] * W[j];
    }
    acc = warp_sum(acc);
    if (lane == 0) y[warp] = acc + b[0];
}

// ------------------------- launch ------------------------------------------------
extern "C" void kernel_launch(void* const* d_in, const int* in_sizes, int n_in,
                              void* d_out, int out_size) {
    const float* x_seq = (const float*)d_in[0];
    const int*   ei    = (const int*)d_in[1];
    const float* W_l0  = (const float*)d_in[2];
    const float* W_r0  = (const float*)d_in[3];
    const float* b0    = (const float*)d_in[4];
    const float* ln0g  = (const float*)d_in[5];
    const float* ln0b  = (const float*)d_in[6];
    const float* W_l1  = (const float*)d_in[7];
    const float* W_r1  = (const float*)d_in[8];
    const float* b1    = (const float*)d_in[9];
    const float* ln1g  = (const float*)d_in[10];
    const float* ln1b  = (const float*)d_in[11];
    const float* Wih   = (const float*)d_in[12];
    const float* Whh   = (const float*)d_in[13];
    const float* bih   = (const float*)d_in[14];
    const float* bhh   = (const float*)d_in[15];
    const float* headW = (const float*)d_in[16];
    const float* headb = (const float*)d_in[17];
    float* y = (float*)d_out;

    const int SMEM_S = 128 * 68  * 2 * 4;   //  69632
    const int SMEM_G = 128 * 100 * 2 * 4;   // 102400
    cudaFuncSetAttribute(k_sage, cudaFuncAttributeMaxDynamicSharedMemorySize, SMEM_S);
    cudaFuncSetAttribute(k_gru,  cudaFuncAttributeMaxDynamicSharedMemorySize, SMEM_G);

    // CSR build (k_scan re-zeroes cnt/fill for graph replays)
    k_hist<<<(N_EDGES + 255) / 256, 256>>>(ei);
    k_scan<<<1, 1024>>>();
    k_scatter<<<(N_EDGES + 255) / 256, 256>>>(ei);

    // phase A
    dim3 gridA((N_NODES + 7) / 8, T_STEPS);
    k_stack0_all<<<gridA, 256>>>(x_seq, W_l0, W_r0, b0, ln0g, ln0b);
    k_prep_ws1<<<(64 * 64 + 255) / 256, 256>>>(W_l1, W_r1);
    k_prep_wg<<<(G3 * 96 + 255) / 256, 256>>>(Wih, Whh);
    k_zero_hid<<<(N_NODES * HT + 255) / 256, 256>>>();
    k_agg1_all<<<gridA, 256>>>();

    k_sage<<<dim3(1, NT / 128), 256, SMEM_S>>>(b1, ln1g, ln1b);

    // phase B: 16 fused gi-GEMM + gh-GEMM + gate steps (t=0 uses hid=0)
    int gridGH = (N_NODES + 127) / 128;   // 157
    for (int t = 0; t < T_STEPS; t++)
        k_gru<<<dim3(2, gridGH), 256, SMEM_G>>>(bih, bhh, t);

    k_head<<<(N_NODES * 32 + 255) / 256, 256>>>(headW, headb, y);
}

// round 11
// speedup vs baseline: 1.4455x; 1.4455x over previous
#include <cuda_runtime.h>
#include <math.h>
#include <stdint.h>

#define N_NODES 20000
#define N_EDGES 320000
#define T_STEPS 16
#define HG 64
#define HT 128
#define G3 384
#define NT (N_NODES * T_STEPS)
#define LN_EPS 1e-5f

// ===================== scratch (static device globals) =======================
__device__ int   g_cnt[N_NODES];
__device__ int   g_fill[N_NODES];
__device__ int   g_rowptr[N_NODES + 1];
__device__ int   g_col[N_EDGES];
__device__ float g_h0_all[NT * HG];
__device__ float g_ins_all[NT * (2 * HG)];
__device__ float g_H_all[NT * HG];
__device__ float g_gi_all[NT * G3];

// pre-split packed-bf16 weights, fragment-contiguous: P[(rb*K2 + c)*8 + (row&7)]
__device__ uint32_t g_ws1h[8  * 64 * 8], g_ws1l[8  * 64 * 8];   // ws1: 64 rows, K2=64
__device__ uint32_t g_wihh[48 * 32 * 8], g_wihl[48 * 32 * 8];   // Wih: 384 rows, K2=32
__device__ uint32_t g_whhh[48 * 64 * 8], g_whhl[48 * 64 * 8];   // Whh: 384 rows, K2=64

__device__ __forceinline__ float warp_sum(float v) {
#pragma unroll
    for (int o = 16; o; o >>= 1) v += __shfl_xor_sync(0xFFFFFFFFu, v, o);
    return v;
}

// bf16x2 split: returns packed hi pair, writes packed lo pair (lo = v - hi)
__device__ __forceinline__ uint32_t pack_split(float x0, float x1, uint32_t& lo) {
    uint32_t hi;
    asm("cvt.rn.bf16x2.f32 %0, %1, %2;" : "=r"(hi) : "f"(x1), "f"(x0));
    float h0 = __uint_as_float(hi << 16);
    float h1 = __uint_as_float(hi & 0xFFFF0000u);
    float l0 = x0 - h0, l1 = x1 - h1;
    asm("cvt.rn.bf16x2.f32 %0, %1, %2;" : "=r"(lo) : "f"(l1), "f"(l0));
    return hi;
}

// m16n8k16 bf16 MMA (sm_80+ generic PTX)
__device__ __forceinline__ void mma16(float* d, const uint32_t* a, uint32_t b0, uint32_t b1) {
    asm volatile(
        "mma.sync.aligned.m16n8k16.row.col.f32.bf16.bf16.f32 "
        "{%0,%1,%2,%3}, {%4,%5,%6,%7}, {%8,%9}, {%0,%1,%2,%3};"
        : "+f"(d[0]), "+f"(d[1]), "+f"(d[2]), "+f"(d[3])
        : "r"(a[0]), "r"(a[1]), "r"(a[2]), "r"(a[3]), "r"(b0), "r"(b1));
}

// ------------------------- CSR build -----------------------------------------
__global__ void k_hist(const int* __restrict__ ei) {
    int e = blockIdx.x * blockDim.x + threadIdx.x;
    if (e < N_EDGES) atomicAdd(&g_cnt[ei[N_EDGES + e]], 1);
}

__global__ void k_scan() {
    __shared__ int sh[1024];
    __shared__ int base;
    int tid = threadIdx.x;
    if (tid == 0) { base = 0; g_rowptr[0] = 0; }
    __syncthreads();
    for (int start = 0; start < N_NODES; start += 1024) {
        int i = start + tid;
        int v = (i < N_NODES) ? g_cnt[i] : 0;
        sh[tid] = v;
        __syncthreads();
        for (int off = 1; off < 1024; off <<= 1) {
            int t = (tid >= off) ? sh[tid - off] : 0;
            __syncthreads();
            sh[tid] += t;
            __syncthreads();
        }
        if (i < N_NODES) g_rowptr[i + 1] = base + sh[tid];
        __syncthreads();
        if (tid == 1023) base += sh[1023];
        __syncthreads();
    }
    for (int i = tid; i < N_NODES; i += 1024) { g_cnt[i] = 0; g_fill[i] = 0; }
}

__global__ void k_scatter(const int* __restrict__ ei) {
    int e = blockIdx.x * blockDim.x + threadIdx.x;
    if (e >= N_EDGES) return;
    int d = ei[N_EDGES + e];
    int p = atomicAdd(&g_fill[d], 1);
    g_col[g_rowptr[d] + p] = ei[e];
}

// ------------------- weight pre-split kernels ---------------------------------
// Destinations referenced in DEVICE code only (GB300/ATS host-shadow trap).
__global__ void k_prep_ws1(const float* __restrict__ Wl1, const float* __restrict__ Wr1) {
    int idx = blockIdx.x * blockDim.x + threadIdx.x;   // 64 * 64
    if (idx >= 64 * 64) return;
    int m = idx >> 6, c = idx & 63;
    int k0 = 2 * c;
    float v0 = (k0 < 64) ? Wl1[k0 * 64 + m] : Wr1[(k0 - 64) * 64 + m];
    float v1 = (k0 + 1 < 64) ? Wl1[(k0 + 1) * 64 + m] : Wr1[(k0 - 63) * 64 + m];
    uint32_t lo, hi = pack_split(v0, v1, lo);
    int o = ((m >> 3) * 64 + c) * 8 + (m & 7);
    g_ws1h[o] = hi; g_ws1l[o] = lo;
}

template <int WSEL, int M, int K>
__global__ void k_prep_w(const float* __restrict__ W) {
    uint32_t* __restrict__ Ph = (WSEL == 0) ? g_wihh : g_whhh;
    uint32_t* __restrict__ Pl = (WSEL == 0) ? g_wihl : g_whhl;
    int idx = blockIdx.x * blockDim.x + threadIdx.x;   // M * K/2
    if (idx >= M * (K / 2)) return;
    int row = idx / (K / 2), c = idx % (K / 2);
    float v0 = W[row * K + 2 * c], v1 = W[row * K + 2 * c + 1];
    uint32_t lo, hi = pack_split(v0, v1, lo);
    int o = ((row >> 3) * (K / 2) + c) * 8 + (row & 7);
    Ph[o] = hi; Pl[o] = lo;
}

// ------------------- layer 0 (batched): agg + SAGE + LN + relu ----------------
__global__ void k_stack0_all(const float* __restrict__ x_seq,
                             const float* __restrict__ Wl, const float* __restrict__ Wr,
                             const float* __restrict__ b0,
                             const float* __restrict__ g, const float* __restrict__ beta) {
    int t = blockIdx.y;
    int n = blockIdx.x * 8 + (threadIdx.x >> 5);
    int lane = threadIdx.x & 31;
    if (n >= N_NODES) return;
    const float* xt = x_seq + t * N_NODES;
    int beg = g_rowptr[n], end = g_rowptr[n + 1];
    float acc = 0.f;
    for (int i = beg + lane; i < end; i += 32) acc += xt[g_col[i]];
    acc = warp_sum(acc);
    float deg = fmaxf((float)(end - beg), 1.f);
    float agg = acc / deg;
    float xv = xt[n];
    float v0 = agg * Wl[lane]      + xv * Wr[lane]      + b0[lane];
    float v1 = agg * Wl[lane + 32] + xv * Wr[lane + 32] + b0[lane + 32];
    float mu = warp_sum(v0 + v1) * (1.f / 64.f);
    float d0 = v0 - mu, d1 = v1 - mu;
    float var = warp_sum(d0 * d0 + d1 * d1) * (1.f / 64.f);
    float inv = rsqrtf(var + LN_EPS);
    float h0a = fmaxf(d0 * inv * g[lane]      + beta[lane], 0.f);
    float h0b = fmaxf(d1 * inv * g[lane + 32] + beta[lane + 32], 0.f);
    size_t row = (size_t)t * N_NODES + n;
    g_h0_all[row * HG + lane]      = h0a;
    g_h0_all[row * HG + lane + 32] = h0b;
    g_ins_all[row * 128 + 64 + lane]      = h0a;
    g_ins_all[row * 128 + 64 + lane + 32] = h0b;
}

// ------------------- layer 1 aggregate (batched, 2-way unrolled) --------------
__global__ void k_agg1_all() {
    int t = blockIdx.y;
    int n = blockIdx.x * 8 + (threadIdx.x >> 5);
    int lane = threadIdx.x & 31;
    if (n >= N_NODES) return;
    const float* h0t = g_h0_all + (size_t)t * N_NODES * HG;
    int beg = g_rowptr[n], end = g_rowptr[n + 1];
    float a0 = 0.f, a1 = 0.f, c0 = 0.f, c1 = 0.f;
    int i = beg;
    for (; i + 1 < end; i += 2) {
        int s0 = g_col[i], s1 = g_col[i + 1];
        a0 += h0t[s0 * HG + lane];
        a1 += h0t[s0 * HG + lane + 32];
        c0 += h0t[s1 * HG + lane];
        c1 += h0t[s1 * HG + lane + 32];
    }
    if (i < end) {
        int s = g_col[i];
        a0 += h0t[s * HG + lane];
        a1 += h0t[s * HG + lane + 32];
    }
    a0 += c0; a1 += c1;
    float inv = 1.f / fmaxf((float)(end - beg), 1.f);
    size_t row = (size_t)t * N_NODES + n;
    g_ins_all[row * 128 + lane]      = a0 * inv;
    g_ins_all[row * 128 + lane + 32] = a1 * inv;
}

// ===================== sage1 bf16x3 GEMM ======================================
// S = ins_all(NTx128) @ ws1^T(64x128); epilogue: +b1, LN, relu -> g_H_all
__global__ void __launch_bounds__(256)
k_sage(const float* __restrict__ bias, const float* __restrict__ p0,
       const float* __restrict__ p1) {
    constexpr int K2  = 64;
    constexpr int LDK = K2 + 4;
    constexpr int BM  = 128;

    extern __shared__ uint32_t smu[];
    uint32_t* Ah = smu;
    uint32_t* Al = Ah + BM * LDK;

    int tid = threadIdx.x;
    int rowBase = blockIdx.y * BM;

    for (int idx = tid; idx < BM * 32; idx += 256) {
        int r = idx >> 5, c4 = idx & 31;
        float4 v = *(const float4*)(g_ins_all + ((size_t)rowBase + r) * 128 + c4 * 4);
        uint32_t lo0, lo1;
        uint32_t hi0 = pack_split(v.x, v.y, lo0);
        uint32_t hi1 = pack_split(v.z, v.w, lo1);
        int j = r * LDK + c4 * 2;
        Ah[j] = hi0; Ah[j + 1] = hi1;
        Al[j] = lo0; Al[j + 1] = lo1;
    }
    __syncthreads();

    int warp = tid >> 5, lane = tid & 31;
    int wm = warp >> 1, wn = warp & 1;           // 4 x 2 warps, WM=32, WN=32
    int g = lane >> 2, tg = lane & 3;
    int m0 = wm * 32, n0 = wn * 32;

    float acc[2][4][4] = {};
#pragma unroll
    for (int kk = 0; kk < K2; kk += 8) {
        uint32_t ah[2][4], al[2][4];
#pragma unroll
        for (int mf = 0; mf < 2; mf++) {
            int base = (m0 + 16 * mf + g) * LDK + kk + tg;
            ah[mf][0] = Ah[base];               al[mf][0] = Al[base];
            ah[mf][1] = Ah[base + 8 * LDK];     al[mf][1] = Al[base + 8 * LDK];
            ah[mf][2] = Ah[base + 4];           al[mf][2] = Al[base + 4];
            ah[mf][3] = Ah[base + 8 * LDK + 4]; al[mf][3] = Al[base + 8 * LDK + 4];
        }
#pragma unroll
        for (int nf = 0; nf < 4; nf++) {
            int nrow = n0 + 8 * nf;
            int fo = ((nrow >> 3) * K2 + kk + tg) * 8 + g;
            uint32_t bh0 = g_ws1h[fo], bh1 = g_ws1h[fo + 32];
            uint32_t bl0 = g_ws1l[fo], bl1 = g_ws1l[fo + 32];
#pragma unroll
            for (int mf = 0; mf < 2; mf++) {
                mma16(acc[mf][nf], al[mf], bh0, bh1);
                mma16(acc[mf][nf], ah[mf], bl0, bl1);
                mma16(acc[mf][nf], ah[mf], bh0, bh1);
            }
        }
    }

    __syncthreads();
    float* S = (float*)smu;                      // 128 x 68
#pragma unroll
    for (int mf = 0; mf < 2; mf++)
#pragma unroll
        for (int nf = 0; nf < 4; nf++) {
            int r = m0 + 16 * mf + g;
            int c = n0 + 8 * nf + 2 * tg;
            S[r * 68 + c]           = acc[mf][nf][0] + bias[c];
            S[r * 68 + c + 1]       = acc[mf][nf][1] + bias[c + 1];
            S[(r + 8) * 68 + c]     = acc[mf][nf][2] + bias[c];
            S[(r + 8) * 68 + c + 1] = acc[mf][nf][3] + bias[c + 1];
        }
    __syncthreads();
#pragma unroll
    for (int i = 0; i < 16; i++) {
        int r = warp * 16 + i;
        float v0 = S[r * 68 + lane];
        float v1 = S[r * 68 + lane + 32];
        float mu = warp_sum(v0 + v1) * (1.f / 64.f);
        float d0 = v0 - mu, d1 = v1 - mu;
        float var = warp_sum(d0 * d0 + d1 * d1) * (1.f / 64.f);
        float inv = rsqrtf(var + LN_EPS);
        size_t rowg = (size_t)rowBase + r;
        g_H_all[rowg * HG + lane]      = fmaxf(d0 * inv * p0[lane]      + p1[lane], 0.f);
        g_H_all[rowg * HG + lane + 32] = fmaxf(d1 * inv * p0[lane + 32] + p1[lane + 32], 0.f);
    }
}

// ===================== gi bf16x3 GEMM (parallel over all t) ===================
// gi_all = H_all(NTx64) @ Wih^T(384x64) + bih
__global__ void __launch_bounds__(256)
k_gi(const float* __restrict__ bias) {
    constexpr int K2  = 32;
    constexpr int LDK = K2 + 4;                  // 36
    constexpr int BM  = 128;

    extern __shared__ uint32_t smu[];
    uint32_t* Ah = smu;
    uint32_t* Al = Ah + BM * LDK;

    int tid = threadIdx.x;
    int rowBase = blockIdx.y * BM;
    int colBase = blockIdx.x * 128;

    for (int idx = tid; idx < BM * 16; idx += 256) {
        int r = idx >> 4, c4 = idx & 15;
        float4 v = *(const float4*)(g_H_all + ((size_t)rowBase + r) * 64 + c4 * 4);
        uint32_t lo0, lo1;
        uint32_t hi0 = pack_split(v.x, v.y, lo0);
        uint32_t hi1 = pack_split(v.z, v.w, lo1);
        int j = r * LDK + c4 * 2;
        Ah[j] = hi0; Ah[j + 1] = hi1;
        Al[j] = lo0; Al[j + 1] = lo1;
    }
    __syncthreads();

    int warp = tid >> 5, lane = tid & 31;
    int wm = warp >> 2, wn = warp & 3;           // 2 x 4 warps, WM=64, WN=32
    int g = lane >> 2, tg = lane & 3;
    int m0 = wm * 64, n0 = wn * 32;

    float acc[4][4][4] = {};
#pragma unroll
    for (int kk = 0; kk < K2; kk += 8) {
        uint32_t ah[4][4], al[4][4];
#pragma unroll
        for (int mf = 0; mf < 4; mf++) {
            int base = (m0 + 16 * mf + g) * LDK + kk + tg;
            ah[mf][0] = Ah[base];               al[mf][0] = Al[base];
            ah[mf][1] = Ah[base + 8 * LDK];     al[mf][1] = Al[base + 8 * LDK];
            ah[mf][2] = Ah[base + 4];           al[mf][2] = Al[base + 4];
            ah[mf][3] = Ah[base + 8 * LDK + 4]; al[mf][3] = Al[base + 8 * LDK + 4];
        }
#pragma unroll
        for (int nf = 0; nf < 4; nf++) {
            int nrow = colBase + n0 + 8 * nf;
            int fo = ((nrow >> 3) * K2 + kk + tg) * 8 + g;
            uint32_t bh0 = g_wihh[fo], bh1 = g_wihh[fo + 32];
            uint32_t bl0 = g_wihl[fo], bl1 = g_wihl[fo + 32];
#pragma unroll
            for (int mf = 0; mf < 4; mf++) {
                mma16(acc[mf][nf], al[mf], bh0, bh1);
                mma16(acc[mf][nf], ah[mf], bl0, bl1);
                mma16(acc[mf][nf], ah[mf], bh0, bh1);
            }
        }
    }

#pragma unroll
    for (int mf = 0; mf < 4; mf++)
#pragma unroll
        for (int nf = 0; nf < 4; nf++) {
            size_t r = (size_t)rowBase + m0 + 16 * mf + g;
            int c = colBase + n0 + 8 * nf + 2 * tg;
            float2 w0 = make_float2(acc[mf][nf][0] + bias[c], acc[mf][nf][1] + bias[c + 1]);
            float2 w1 = make_float2(acc[mf][nf][2] + bias[c], acc[mf][nf][3] + bias[c + 1]);
            *(float2*)(g_gi_all + r * G3 + c)       = w0;
            *(float2*)(g_gi_all + (r + 8) * G3 + c) = w1;
        }
}

// ===================== persistent GRU chain ====================================
// One launch. CTA owns 32 nodes; loops t=0..15 with h resident in smem.
// Per step: pack-split h -> smem bf16 A, bf16x3 MMA vs pre-split Whh (L2),
// epilogue: gates with gi_all[t] slice, h updated in smem. Head fused at end.
__global__ void __launch_bounds__(256, 2)
k_chain(const float* __restrict__ bhh, const float* __restrict__ headW,
        const float* __restrict__ headb, float* __restrict__ y) {
    constexpr int K2  = 64;
    constexpr int LDK = 68;
    constexpr int BM  = 32;                     // 20000 = 625 * 32 exactly

    __shared__ float    hs[BM][HT + 4];         // padded vs bank conflicts
    __shared__ uint32_t Ah[BM * LDK];
    __shared__ uint32_t Al[BM * LDK];

    int tid = threadIdx.x, warp = tid >> 5, lane = tid & 31;
    int nodeBase = blockIdx.x * BM;
    int g = lane >> 2, tg = lane & 3;
    int n0 = warp * 16;                         // 8 warps x WN=16 over 128 cols

    for (int i = tid; i < BM * HT; i += 256) hs[i >> 7][i & 127] = 0.f;
    __syncthreads();

    for (int t = 0; t < T_STEPS; t++) {
        float acc[3][2][2][4] = {};             // [gate][MF][NF][4]
        if (t > 0) {
            // ---- stage A: hs -> packed bf16 hi/lo ----
            for (int i = tid; i < BM * 32; i += 256) {
                int r = i >> 5, c4 = i & 31;
                float4 v = *(const float4*)(&hs[r][c4 * 4]);
                uint32_t lo0, lo1;
                uint32_t hi0 = pack_split(v.x, v.y, lo0);
                uint32_t hi1 = pack_split(v.z, v.w, lo1);
                int j = r * LDK + c4 * 2;
                Ah[j] = hi0; Ah[j + 1] = hi1;
                Al[j] = lo0; Al[j + 1] = lo1;
            }
            __syncthreads();
#pragma unroll
            for (int kk = 0; kk < K2; kk += 8) {
                uint32_t ah[2][4], al[2][4];
#pragma unroll
                for (int mf = 0; mf < 2; mf++) {
                    int base = (16 * mf + g) * LDK + kk + tg;
                    ah[mf][0] = Ah[base];               al[mf][0] = Al[base];
                    ah[mf][1] = Ah[base + 8 * LDK];     al[mf][1] = Al[base + 8 * LDK];
                    ah[mf][2] = Ah[base + 4];           al[mf][2] = Al[base + 4];
                    ah[mf][3] = Ah[base + 8 * LDK + 4]; al[mf][3] = Al[base + 8 * LDK + 4];
                }
#pragma unroll
                for (int gt = 0; gt < 3; gt++)
#pragma unroll
                    for (int nf = 0; nf < 2; nf++) {
                        int nrow = gt * HT + n0 + 8 * nf;
                        int fo = ((nrow >> 3) * K2 + kk + tg) * 8 + g;
                        uint32_t bh0 = g_whhh[fo], bh1 = g_whhh[fo + 32];
                        uint32_t bl0 = g_whhl[fo], bl1 = g_whhl[fo + 32];
#pragma unroll
                        for (int mf = 0; mf < 2; mf++) {
                            mma16(acc[gt][mf][nf], al[mf], bh0, bh1);
                            mma16(acc[gt][mf][nf], ah[mf], bl0, bl1);
                            mma16(acc[gt][mf][nf], ah[mf], bh0, bh1);
                        }
                    }
            }
        }
        // ---- gates epilogue (gi includes bih already) ----
#pragma unroll
        for (int mf = 0; mf < 2; mf++)
#pragma unroll
            for (int nf = 0; nf < 2; nf++)
#pragma unroll
                for (int half = 0; half < 2; half++) {
                    int nl = 16 * mf + g + 8 * half;
                    int c = n0 + 8 * nf + 2 * tg;
                    const float* gi = g_gi_all +
                        ((size_t)t * N_NODES + nodeBase + nl) * G3 + c;
                    float2 gir = *(const float2*)gi;
                    float2 giz = *(const float2*)(gi + 128);
                    float2 gin = *(const float2*)(gi + 256);
                    int h2 = half * 2;
                    float r0 = 1.f / (1.f + __expf(-(gir.x + acc[0][mf][nf][h2]     + bhh[c])));
                    float r1 = 1.f / (1.f + __expf(-(gir.y + acc[0][mf][nf][h2 + 1] + bhh[c + 1])));
                    float z0 = 1.f / (1.f + __expf(-(giz.x + acc[1][mf][nf][h2]     + bhh[128 + c])));
                    float z1 = 1.f / (1.f + __expf(-(giz.y + acc[1][mf][nf][h2 + 1] + bhh[128 + c + 1])));
                    float n0v = tanhf(gin.x + r0 * (acc[2][mf][nf][h2]     + bhh[256 + c]));
                    float n1v = tanhf(gin.y + r1 * (acc[2][mf][nf][h2 + 1] + bhh[256 + c + 1]));
                    float hx = hs[nl][c], hy = hs[nl][c + 1];
                    hs[nl][c]     = (1.f - z0) * n0v + z0 * hx;
                    hs[nl][c + 1] = (1.f - z1) * n1v + z1 * hy;
                }
        __syncthreads();
    }

    // ---- fused head: y[node] = dot(h, headW) + headb ----
#pragma unroll
    for (int i = 0; i < 4; i++) {
        int r = warp * 4 + i;
        float acc = 0.f;
#pragma unroll
        for (int q = 0; q < 4; q++) {
            int j = lane + 32 * q;
            acc += hs[r][j] * headW[j];
        }
        acc = warp_sum(acc);
        if (lane == 0) y[nodeBase + r] = acc + headb[0];
    }
}

// ------------------------- launch ------------------------------------------------
extern "C" void kernel_launch(void* const* d_in, const int* in_sizes, int n_in,
                              void* d_out, int out_size) {
    const float* x_seq = (const float*)d_in[0];
    const int*   ei    = (const int*)d_in[1];
    const float* W_l0  = (const float*)d_in[2];
    const float* W_r0  = (const float*)d_in[3];
    const float* b0    = (const float*)d_in[4];
    const float* ln0g  = (const float*)d_in[5];
    const float* ln0b  = (const float*)d_in[6];
    const float* W_l1  = (const float*)d_in[7];
    const float* W_r1  = (const float*)d_in[8];
    const float* b1    = (const float*)d_in[9];
    const float* ln1g  = (const float*)d_in[10];
    const float* ln1b  = (const float*)d_in[11];
    const float* Wih   = (const float*)d_in[12];
    const float* Whh   = (const float*)d_in[13];
    const float* bih   = (const float*)d_in[14];
    const float* bhh   = (const float*)d_in[15];
    const float* headW = (const float*)d_in[16];
    const float* headb = (const float*)d_in[17];
    float* y = (float*)d_out;

    const int SMEM_S = 128 * 68 * 2 * 4;   // 69632
    const int SMEM_G = 128 * 36 * 2 * 4;   // 36864
    cudaFuncSetAttribute(k_sage, cudaFuncAttributeMaxDynamicSharedMemorySize, SMEM_S);
    cudaFuncSetAttribute(k_gi,   cudaFuncAttributeMaxDynamicSharedMemorySize, SMEM_G);

    // CSR build (k_scan re-zeroes cnt/fill for graph replays)
    k_hist<<<(N_EDGES + 255) / 256, 256>>>(ei);
    k_scan<<<1, 1024>>>();
    k_scatter<<<(N_EDGES + 255) / 256, 256>>>(ei);

    // phase A (all timesteps in parallel)
    dim3 gridA((N_NODES + 7) / 8, T_STEPS);
    k_stack0_all<<<gridA, 256>>>(x_seq, W_l0, W_r0, b0, ln0g, ln0b);
    k_prep_ws1<<<(64 * 64 + 255) / 256, 256>>>(W_l1, W_r1);
    k_prep_w<0, G3, 64><<<(G3 * 32 + 255) / 256, 256>>>(Wih);
    k_prep_w<1, G3, 128><<<(G3 * 64 + 255) / 256, 256>>>(Whh);
    k_agg1_all<<<gridA, 256>>>();

    k_sage<<<dim3(1, NT / 128), 256, SMEM_S>>>(b1, ln1g, ln1b);
    k_gi<<<dim3(G3 / 128, NT / 128), 256, SMEM_G>>>(bih);

    // phase B: single persistent-chain launch (GRU + head fused)
    k_chain<<<N_NODES / 32, 256>>>(bhh, headW, headb, y);
}

// round 12
// speedup vs baseline: 1.6225x; 1.1224x over previous
#include <cuda_runtime.h>
#include <math.h>
#include <stdint.h>

#define N_NODES 20000
#define N_EDGES 320000
#define T_STEPS 16
#define HG 64
#define HT 128
#define G3 384
#define NT (N_NODES * T_STEPS)
#define LN_EPS 1e-5f

// ===================== scratch (static device globals) =======================
__device__ int   g_cnt[N_NODES];
__device__ int   g_fill[N_NODES];
__device__ int   g_rowptr[N_NODES + 1];
__device__ int   g_col[N_EDGES];
__device__ float g_h0_all[NT * HG];
__device__ float g_ins_all[NT * (2 * HG)];
__device__ float g_gi_all[NT * G3];

// pre-split packed-bf16 weights, hi/lo interleaved (uint2), fragment-contiguous:
// P[(rowblk*K2 + c)*8 + (row&7)] = {hi, lo}
__device__ uint2 g_ws1p[8  * 64 * 8];   // ws1: 64 rows, K2=64
__device__ uint2 g_wihp[48 * 32 * 8];   // Wih: 384 rows, K2=32
__device__ uint2 g_whhp[48 * 64 * 8];   // Whh: 384 rows, K2=64

__device__ __forceinline__ float warp_sum(float v) {
#pragma unroll
    for (int o = 16; o; o >>= 1) v += __shfl_xor_sync(0xFFFFFFFFu, v, o);
    return v;
}

// bf16x2 split: returns packed hi pair, writes packed lo pair (lo = v - hi)
__device__ __forceinline__ uint32_t pack_split(float x0, float x1, uint32_t& lo) {
    uint32_t hi;
    asm("cvt.rn.bf16x2.f32 %0, %1, %2;" : "=r"(hi) : "f"(x1), "f"(x0));
    float h0 = __uint_as_float(hi << 16);
    float h1 = __uint_as_float(hi & 0xFFFF0000u);
    float l0 = x0 - h0, l1 = x1 - h1;
    asm("cvt.rn.bf16x2.f32 %0, %1, %2;" : "=r"(lo) : "f"(l1), "f"(l0));
    return hi;
}

// m16n8k16 bf16 MMA (sm_80+ generic PTX)
__device__ __forceinline__ void mma16(float* d, const uint32_t* a, uint32_t b0, uint32_t b1) {
    asm volatile(
        "mma.sync.aligned.m16n8k16.row.col.f32.bf16.bf16.f32 "
        "{%0,%1,%2,%3}, {%4,%5,%6,%7}, {%8,%9}, {%0,%1,%2,%3};"
        : "+f"(d[0]), "+f"(d[1]), "+f"(d[2]), "+f"(d[3])
        : "r"(a[0]), "r"(a[1]), "r"(a[2]), "r"(a[3]), "r"(b0), "r"(b1));
}

// bf16x3 against interleaved fragments
__device__ __forceinline__ void mma_x3(float* d, const uint32_t* ah, const uint32_t* al,
                                       uint2 w0, uint2 w1) {
    mma16(d, al, w0.x, w1.x);   // lo_A * hi_B (small terms first)
    mma16(d, ah, w0.y, w1.y);   // hi_A * lo_B
    mma16(d, ah, w0.x, w1.x);   // hi_A * hi_B
}

// ------------------------- CSR build -----------------------------------------
__global__ void k_hist(const int* __restrict__ ei) {
    int e = blockIdx.x * blockDim.x + threadIdx.x;
    if (e < N_EDGES) atomicAdd(&g_cnt[ei[N_EDGES + e]], 1);
}

__global__ void k_scan() {
    __shared__ int sh[1024];
    __shared__ int base;
    int tid = threadIdx.x;
    if (tid == 0) { base = 0; g_rowptr[0] = 0; }
    __syncthreads();
    for (int start = 0; start < N_NODES; start += 1024) {
        int i = start + tid;
        int v = (i < N_NODES) ? g_cnt[i] : 0;
        sh[tid] = v;
        __syncthreads();
        for (int off = 1; off < 1024; off <<= 1) {
            int t = (tid >= off) ? sh[tid - off] : 0;
            __syncthreads();
            sh[tid] += t;
            __syncthreads();
        }
        if (i < N_NODES) g_rowptr[i + 1] = base + sh[tid];
        __syncthreads();
        if (tid == 1023) base += sh[1023];
        __syncthreads();
    }
    for (int i = tid; i < N_NODES; i += 1024) { g_cnt[i] = 0; g_fill[i] = 0; }
}

__global__ void k_scatter(const int* __restrict__ ei) {
    int e = blockIdx.x * blockDim.x + threadIdx.x;
    if (e >= N_EDGES) return;
    int d = ei[N_EDGES + e];
    int p = atomicAdd(&g_fill[d], 1);
    g_col[g_rowptr[d] + p] = ei[e];
}

// ------------------- weight pre-split kernels ---------------------------------
// Destinations referenced in DEVICE code only (GB300/ATS host-shadow trap).
__global__ void k_prep_ws1(const float* __restrict__ Wl1, const float* __restrict__ Wr1) {
    int idx = blockIdx.x * blockDim.x + threadIdx.x;   // 64 * 64
    if (idx >= 64 * 64) return;
    int m = idx >> 6, c = idx & 63;
    int k0 = 2 * c;
    float v0 = (k0 < 64) ? Wl1[k0 * 64 + m] : Wr1[(k0 - 64) * 64 + m];
    float v1 = (k0 + 1 < 64) ? Wl1[(k0 + 1) * 64 + m] : Wr1[(k0 - 63) * 64 + m];
    uint32_t lo, hi = pack_split(v0, v1, lo);
    g_ws1p[((m >> 3) * 64 + c) * 8 + (m & 7)] = make_uint2(hi, lo);
}

template <int WSEL, int M, int K>
__global__ void k_prep_w(const float* __restrict__ W) {
    uint2* __restrict__ P = (WSEL == 0) ? g_wihp : g_whhp;
    int idx = blockIdx.x * blockDim.x + threadIdx.x;   // M * K/2
    if (idx >= M * (K / 2)) return;
    int row = idx / (K / 2), c = idx % (K / 2);
    float v0 = W[row * K + 2 * c], v1 = W[row * K + 2 * c + 1];
    uint32_t lo, hi = pack_split(v0, v1, lo);
    P[((row >> 3) * (K / 2) + c) * 8 + (row & 7)] = make_uint2(hi, lo);
}

// ------------------- layer 0 (batched): agg + SAGE + LN + relu ----------------
__global__ void k_stack0_all(const float* __restrict__ x_seq,
                             const float* __restrict__ Wl, const float* __restrict__ Wr,
                             const float* __restrict__ b0,
                             const float* __restrict__ g, const float* __restrict__ beta) {
    int t = blockIdx.y;
    int n = blockIdx.x * 8 + (threadIdx.x >> 5);
    int lane = threadIdx.x & 31;
    if (n >= N_NODES) return;
    const float* xt = x_seq + t * N_NODES;
    int beg = g_rowptr[n], end = g_rowptr[n + 1];
    float acc = 0.f;
    for (int i = beg + lane; i < end; i += 32) acc += xt[g_col[i]];
    acc = warp_sum(acc);
    float deg = fmaxf((float)(end - beg), 1.f);
    float agg = acc / deg;
    float xv = xt[n];
    float v0 = agg * Wl[lane]      + xv * Wr[lane]      + b0[lane];
    float v1 = agg * Wl[lane + 32] + xv * Wr[lane + 32] + b0[lane + 32];
    float mu = warp_sum(v0 + v1) * (1.f / 64.f);
    float d0 = v0 - mu, d1 = v1 - mu;
    float var = warp_sum(d0 * d0 + d1 * d1) * (1.f / 64.f);
    float inv = rsqrtf(var + LN_EPS);
    float h0a = fmaxf(d0 * inv * g[lane]      + beta[lane], 0.f);
    float h0b = fmaxf(d1 * inv * g[lane + 32] + beta[lane + 32], 0.f);
    size_t row = (size_t)t * N_NODES + n;
    g_h0_all[row * HG + lane]      = h0a;
    g_h0_all[row * HG + lane + 32] = h0b;
    g_ins_all[row * 128 + 64 + lane]      = h0a;
    g_ins_all[row * 128 + 64 + lane + 32] = h0b;
}

// ------------------- layer 1 aggregate (batched, 2-way unrolled) --------------
__global__ void k_agg1_all() {
    int t = blockIdx.y;
    int n = blockIdx.x * 8 + (threadIdx.x >> 5);
    int lane = threadIdx.x & 31;
    if (n >= N_NODES) return;
    const float* h0t = g_h0_all + (size_t)t * N_NODES * HG;
    int beg = g_rowptr[n], end = g_rowptr[n + 1];
    float a0 = 0.f, a1 = 0.f, c0 = 0.f, c1 = 0.f;
    int i = beg;
    for (; i + 1 < end; i += 2) {
        int s0 = g_col[i], s1 = g_col[i + 1];
        a0 += h0t[s0 * HG + lane];
        a1 += h0t[s0 * HG + lane + 32];
        c0 += h0t[s1 * HG + lane];
        c1 += h0t[s1 * HG + lane + 32];
    }
    if (i < end) {
        int s = g_col[i];
        a0 += h0t[s * HG + lane];
        a1 += h0t[s * HG + lane + 32];
    }
    a0 += c0; a1 += c1;
    float inv = 1.f / fmaxf((float)(end - beg), 1.f);
    size_t row = (size_t)t * N_NODES + n;
    g_ins_all[row * 128 + lane]      = a0 * inv;
    g_ins_all[row * 128 + lane + 32] = a1 * inv;
}

// ===================== fused sage + gi GEMM ====================================
// Phase 1: S = ins_all(128x128) @ ws1^T(64x128) + b1; LN+relu -> H (smem only)
// Phase 2: gi = H(128x64) @ Wih^T(384x64) + bih -> g_gi_all
// smem (u32 units): [0, 8704)   Ah (phase1) / S f32 (LN)
//                   [8704, 17408) Al (phase1)
//                   [8704, 13312) Ah2 (phase2, after S freed? no — see below)
// S aliases Ah only; Ah2/Al2 live at [8704, 17920) — beyond Al is fine.
__global__ void __launch_bounds__(256)
k_sgi(const float* __restrict__ b1, const float* __restrict__ p0,
      const float* __restrict__ p1, const float* __restrict__ bih) {
    constexpr int LDK1 = 68;                   // phase1 K2=64
    constexpr int LDK2 = 36;                   // phase2 K2=32
    constexpr int BM   = 128;

    extern __shared__ uint32_t smu[];
    uint32_t* Ah  = smu;                       // 128*68 = 8704
    uint32_t* Al  = smu + BM * LDK1;           // 8704
    float*    S   = (float*)smu;               // aliases Ah (after phase-1 MMAs)
    uint32_t* Ah2 = smu + BM * LDK1;           // aliases Al (after phase-1 MMAs)
    uint32_t* Al2 = Ah2 + BM * LDK2;           // 4608, ends at 17920

    int tid = threadIdx.x;
    size_t rowBase = (size_t)blockIdx.x * BM;

    // ---- phase 1 staging: ins_all -> Ah/Al ----
    for (int idx = tid; idx < BM * 32; idx += 256) {
        int r = idx >> 5, c4 = idx & 31;
        float4 v = *(const float4*)(g_ins_all + (rowBase + r) * 128 + c4 * 4);
        uint32_t lo0, lo1;
        uint32_t hi0 = pack_split(v.x, v.y, lo0);
        uint32_t hi1 = pack_split(v.z, v.w, lo1);
        int j = r * LDK1 + c4 * 2;
        Ah[j] = hi0; Ah[j + 1] = hi1;
        Al[j] = lo0; Al[j + 1] = lo1;
    }
    __syncthreads();

    int warp = tid >> 5, lane = tid & 31;
    int g = lane >> 2, tg = lane & 3;

    // ---- phase 1 MMA: 4x2 warps, WM=32, WN=32 ----
    {
        int wm = warp >> 1, wn = warp & 1;
        int m0 = wm * 32, n0 = wn * 32;
        float acc[2][4][4] = {};
#pragma unroll
        for (int kk = 0; kk < 64; kk += 8) {
            uint32_t ah[2][4], al[2][4];
#pragma unroll
            for (int mf = 0; mf < 2; mf++) {
                int base = (m0 + 16 * mf + g) * LDK1 + kk + tg;
                ah[mf][0] = Ah[base];                al[mf][0] = Al[base];
                ah[mf][1] = Ah[base + 8 * LDK1];     al[mf][1] = Al[base + 8 * LDK1];
                ah[mf][2] = Ah[base + 4];            al[mf][2] = Al[base + 4];
                ah[mf][3] = Ah[base + 8 * LDK1 + 4]; al[mf][3] = Al[base + 8 * LDK1 + 4];
            }
#pragma unroll
            for (int nf = 0; nf < 4; nf++) {
                int fo = (((n0 + 8 * nf) >> 3) * 64 + kk + tg) * 8 + g;
                uint2 w0 = g_ws1p[fo], w1 = g_ws1p[fo + 32];
#pragma unroll
                for (int mf = 0; mf < 2; mf++)
                    mma_x3(acc[mf][nf], ah[mf], al[mf], w0, w1);
            }
        }
        __syncthreads();                        // done reading Ah/Al
#pragma unroll
        for (int mf = 0; mf < 2; mf++)
#pragma unroll
            for (int nf = 0; nf < 4; nf++) {
                int r = m0 + 16 * mf + g;
                int c = n0 + 8 * nf + 2 * tg;
                S[r * 68 + c]           = acc[mf][nf][0] + b1[c];
                S[r * 68 + c + 1]       = acc[mf][nf][1] + b1[c + 1];
                S[(r + 8) * 68 + c]     = acc[mf][nf][2] + b1[c];
                S[(r + 8) * 68 + c + 1] = acc[mf][nf][3] + b1[c + 1];
            }
        __syncthreads();
        // ---- LN + relu, H written back into S in place ----
#pragma unroll
        for (int i = 0; i < 16; i++) {
            int r = warp * 16 + i;
            float v0 = S[r * 68 + lane];
            float v1 = S[r * 68 + lane + 32];
            float mu = warp_sum(v0 + v1) * (1.f / 64.f);
            float d0 = v0 - mu, d1 = v1 - mu;
            float var = warp_sum(d0 * d0 + d1 * d1) * (1.f / 64.f);
            float inv = rsqrtf(var + LN_EPS);
            S[r * 68 + lane]      = fmaxf(d0 * inv * p0[lane]      + p1[lane], 0.f);
            S[r * 68 + lane + 32] = fmaxf(d1 * inv * p0[lane + 32] + p1[lane + 32], 0.f);
        }
        __syncthreads();
    }

    // ---- phase 2 staging: H (in S) -> Ah2/Al2 ----
    for (int idx = tid; idx < BM * 16; idx += 256) {
        int r = idx >> 4, c4 = idx & 15;
        float4 v = *(const float4*)(S + r * 68 + c4 * 4);
        uint32_t lo0, lo1;
        uint32_t hi0 = pack_split(v.x, v.y, lo0);
        uint32_t hi1 = pack_split(v.z, v.w, lo1);
        int j = r * LDK2 + c4 * 2;
        Ah2[j] = hi0; Ah2[j + 1] = hi1;
        Al2[j] = lo0; Al2[j + 1] = lo1;
    }
    __syncthreads();

    // ---- phase 2 MMA: 2x4 warps, WM=64, WN=32; loop over 3 col-chunks ----
    {
        int wm = warp >> 2, wn = warp & 3;
        int m0 = wm * 64, n0 = wn * 32;
        uint32_t ah[4][4], al[4][4];
#pragma unroll
        for (int mf = 0; mf < 4; mf++) {        // K2=32: all fragments fit, load once
#pragma unroll
            for (int kq = 0; kq < 2; kq++) {
                int base = (m0 + 16 * mf + g) * LDK2 + kq * 8 + tg;
                // pack two kk-halves into the 4-reg layout per kk below instead
            }
        }
        for (int ch = 0; ch < 3; ch++) {
            float acc[4][4][4];
#pragma unroll
            for (int mf = 0; mf < 4; mf++)
#pragma unroll
                for (int nf = 0; nf < 4; nf++)
#pragma unroll
                    for (int q = 0; q < 4; q++) acc[mf][nf][q] = 0.f;
#pragma unroll
            for (int kk = 0; kk < 32; kk += 8) {
#pragma unroll
                for (int mf = 0; mf < 4; mf++) {
                    int base = (m0 + 16 * mf + g) * LDK2 + kk + tg;
                    ah[mf][0] = Ah2[base];                al[mf][0] = Al2[base];
                    ah[mf][1] = Ah2[base + 8 * LDK2];     al[mf][1] = Al2[base + 8 * LDK2];
                    ah[mf][2] = Ah2[base + 4];            al[mf][2] = Al2[base + 4];
                    ah[mf][3] = Ah2[base + 8 * LDK2 + 4]; al[mf][3] = Al2[base + 8 * LDK2 + 4];
                }
#pragma unroll
                for (int nf = 0; nf < 4; nf++) {
                    int nrow = ch * 128 + n0 + 8 * nf;
                    int fo = ((nrow >> 3) * 32 + kk + tg) * 8 + g;
                    uint2 w0 = g_wihp[fo], w1 = g_wihp[fo + 32];
#pragma unroll
                    for (int mf = 0; mf < 4; mf++)
                        mma_x3(acc[mf][nf], ah[mf], al[mf], w0, w1);
                }
            }
#pragma unroll
            for (int mf = 0; mf < 4; mf++)
#pragma unroll
                for (int nf = 0; nf < 4; nf++) {
                    size_t r = rowBase + m0 + 16 * mf + g;
                    int c = ch * 128 + n0 + 8 * nf + 2 * tg;
                    float2 w0 = make_float2(acc[mf][nf][0] + bih[c], acc[mf][nf][1] + bih[c + 1]);
                    float2 w1 = make_float2(acc[mf][nf][2] + bih[c], acc[mf][nf][3] + bih[c + 1]);
                    *(float2*)(g_gi_all + r * G3 + c)       = w0;
                    *(float2*)(g_gi_all + (r + 8) * G3 + c) = w1;
                }
        }
    }
}

// ===================== persistent GRU chain ====================================
// One launch. CTA owns 32 nodes; loops t=0..15 with h resident in smem.
__global__ void __launch_bounds__(256, 2)
k_chain(const float* __restrict__ bhh, const float* __restrict__ headW,
        const float* __restrict__ headb, float* __restrict__ y) {
    constexpr int K2  = 64;
    constexpr int LDK = 68;
    constexpr int BM  = 32;                     // 20000 = 625 * 32 exactly

    __shared__ float    hs[BM][HT + 4];
    __shared__ uint32_t Ah[BM * LDK];
    __shared__ uint32_t Al[BM * LDK];

    int tid = threadIdx.x, warp = tid >> 5, lane = tid & 31;
    int nodeBase = blockIdx.x * BM;
    int g = lane >> 2, tg = lane & 3;
    int n0 = warp * 16;                         // 8 warps x WN=16 over 128 cols

    for (int i = tid; i < BM * HT; i += 256) hs[i >> 7][i & 127] = 0.f;
    __syncthreads();

    for (int t = 0; t < T_STEPS; t++) {
        // ---- L2 prefetch of this step's gi slice (48KB = 384 lines) ----
        {
            const char* gp = (const char*)(g_gi_all + ((size_t)t * N_NODES + nodeBase) * G3);
            for (int i = tid; i < 384; i += 256)
                asm volatile("prefetch.global.L2 [%0];" :: "l"(gp + (size_t)i * 128));
        }
        float acc[3][2][2][4] = {};             // [gate][MF][NF][4]
        if (t > 0) {
            for (int i = tid; i < BM * 32; i += 256) {
                int r = i >> 5, c4 = i & 31;
                float4 v = *(const float4*)(&hs[r][c4 * 4]);
                uint32_t lo0, lo1;
                uint32_t hi0 = pack_split(v.x, v.y, lo0);
                uint32_t hi1 = pack_split(v.z, v.w, lo1);
                int j = r * LDK + c4 * 2;
                Ah[j] = hi0; Ah[j + 1] = hi1;
                Al[j] = lo0; Al[j + 1] = lo1;
            }
            __syncthreads();
#pragma unroll
            for (int kk = 0; kk < K2; kk += 8) {
                uint32_t ah[2][4], al[2][4];
#pragma unroll
                for (int mf = 0; mf < 2; mf++) {
                    int base = (16 * mf + g) * LDK + kk + tg;
                    ah[mf][0] = Ah[base];               al[mf][0] = Al[base];
                    ah[mf][1] = Ah[base + 8 * LDK];     al[mf][1] = Al[base + 8 * LDK];
                    ah[mf][2] = Ah[base + 4];           al[mf][2] = Al[base + 4];
                    ah[mf][3] = Ah[base + 8 * LDK + 4]; al[mf][3] = Al[base + 8 * LDK + 4];
                }
#pragma unroll
                for (int gt = 0; gt < 3; gt++)
#pragma unroll
                    for (int nf = 0; nf < 2; nf++) {
                        int nrow = gt * HT + n0 + 8 * nf;
                        int fo = ((nrow >> 3) * K2 + kk + tg) * 8 + g;
                        uint2 w0 = g_whhp[fo], w1 = g_whhp[fo + 32];
#pragma unroll
                        for (int mf = 0; mf < 2; mf++)
                            mma_x3(acc[gt][mf][nf], ah[mf], al[mf], w0, w1);
                    }
            }
        }
        // ---- gates epilogue (gi includes bih already) ----
#pragma unroll
        for (int mf = 0; mf < 2; mf++)
#pragma unroll
            for (int nf = 0; nf < 2; nf++)
#pragma unroll
                for (int half = 0; half < 2; half++) {
                    int nl = 16 * mf + g + 8 * half;
                    int c = n0 + 8 * nf + 2 * tg;
                    const float* gi = g_gi_all +
                        ((size_t)t * N_NODES + nodeBase + nl) * G3 + c;
                    float2 gir = *(const float2*)gi;
                    float2 giz = *(const float2*)(gi + 128);
                    float2 gin = *(const float2*)(gi + 256);
                    int h2 = half * 2;
                    float r0 = 1.f / (1.f + __expf(-(gir.x + acc[0][mf][nf][h2]     + bhh[c])));
                    float r1 = 1.f / (1.f + __expf(-(gir.y + acc[0][mf][nf][h2 + 1] + bhh[c + 1])));
                    float z0 = 1.f / (1.f + __expf(-(giz.x + acc[1][mf][nf][h2]     + bhh[128 + c])));
                    float z1 = 1.f / (1.f + __expf(-(giz.y + acc[1][mf][nf][h2 + 1] + bhh[128 + c + 1])));
                    float n0v = tanhf(gin.x + r0 * (acc[2][mf][nf][h2]     + bhh[256 + c]));
                    float n1v = tanhf(gin.y + r1 * (acc[2][mf][nf][h2 + 1] + bhh[256 + c + 1]));
                    float hx = hs[nl][c], hy = hs[nl][c + 1];
                    hs[nl][c]     = (1.f - z0) * n0v + z0 * hx;
                    hs[nl][c + 1] = (1.f - z1) * n1v + z1 * hy;
                }
        __syncthreads();
    }

    // ---- fused head ----
#pragma unroll
    for (int i = 0; i < 4; i++) {
        int r = warp * 4 + i;
        float acc = 0.f;
#pragma unroll
        for (int q = 0; q < 4; q++) {
            int j = lane + 32 * q;
            acc += hs[r][j] * headW[j];
        }
        acc = warp_sum(acc);
        if (lane == 0) y[nodeBase + r] = acc + headb[0];
    }
}

// ------------------------- launch ------------------------------------------------
extern "C" void kernel_launch(void* const* d_in, const int* in_sizes, int n_in,
                              void* d_out, int out_size) {
    const float* x_seq = (const float*)d_in[0];
    const int*   ei    = (const int*)d_in[1];
    const float* W_l0  = (const float*)d_in[2];
    const float* W_r0  = (const float*)d_in[3];
    const float* b0    = (const float*)d_in[4];
    const float* ln0g  = (const float*)d_in[5];
    const float* ln0b  = (const float*)d_in[6];
    const float* W_l1  = (const float*)d_in[7];
    const float* W_r1  = (const float*)d_in[8];
    const float* b1    = (const float*)d_in[9];
    const float* ln1g  = (const float*)d_in[10];
    const float* ln1b  = (const float*)d_in[11];
    const float* Wih   = (const float*)d_in[12];
    const float* Whh   = (const float*)d_in[13];
    const float* bih   = (const float*)d_in[14];
    const float* bhh   = (const float*)d_in[15];
    const float* headW = (const float*)d_in[16];
    const float* headb = (const float*)d_in[17];
    float* y = (float*)d_out;

    const int SMEM_SGI = (128 * 68 + 128 * 36 * 2) * 4;   // 71680
    cudaFuncSetAttribute(k_sgi, cudaFuncAttributeMaxDynamicSharedMemorySize, SMEM_SGI);

    // CSR build (k_scan re-zeroes cnt/fill for graph replays)
    k_hist<<<(N_EDGES + 255) / 256, 256>>>(ei);
    k_scan<<<1, 1024>>>();
    k_scatter<<<(N_EDGES + 255) / 256, 256>>>(ei);

    // phase A (all timesteps in parallel)
    dim3 gridA((N_NODES + 7) / 8, T_STEPS);
    k_stack0_all<<<gridA, 256>>>(x_seq, W_l0, W_r0, b0, ln0g, ln0b);
    k_prep_ws1<<<(64 * 64 + 255) / 256, 256>>>(W_l1, W_r1);
    k_prep_w<0, G3, 64><<<(G3 * 32 + 255) / 256, 256>>>(Wih);
    k_prep_w<1, G3, 128><<<(G3 * 64 + 255) / 256, 256>>>(Whh);
    k_agg1_all<<<gridA, 256>>>();

    k_sgi<<<NT / 128, 256, SMEM_SGI>>>(b1, ln1g, ln1b, bih);

    // phase B: single persistent-chain launch (GRU + head fused)
    k_chain<<<N_NODES / 32, 256>>>(bhh, headW, headb, y);
}

// round 13
// speedup vs baseline: 1.7945x; 1.1060x over previous
#include <cuda_runtime.h>
#include <math.h>
#include <stdint.h>

#define N_NODES 20000
#define N_EDGES 320000
#define T_STEPS 16
#define HG 64
#define HT 128
#define G3 384
#define NT (N_NODES * T_STEPS)
#define LN_EPS 1e-5f

// ===================== scratch (static device globals) =======================
__device__ int   g_cnt[N_NODES];
__device__ int   g_fill[N_NODES];
__device__ int   g_rowptr[N_NODES + 1];
__device__ int   g_col[N_EDGES];
__device__ float g_h0_all[NT * HG];
__device__ float g_ins_all[NT * (2 * HG)];
__device__ float g_H_all[NT * HG];

// pre-split packed-bf16 weights, hi/lo interleaved (uint2), fragment-contiguous:
// P[(rowblk*K2 + c)*8 + (row&7)] = {hi, lo}
__device__ uint2 g_ws1p[8  * 64 * 8];   // ws1: 64 rows, K2=64
__device__ uint2 g_wgp[48 * 96 * 8];    // [Wih|Whh]: 384 rows, K=192, K2=96

__device__ __forceinline__ float warp_sum(float v) {
#pragma unroll
    for (int o = 16; o; o >>= 1) v += __shfl_xor_sync(0xFFFFFFFFu, v, o);
    return v;
}

// bf16x2 split: returns packed hi pair, writes packed lo pair (lo = v - hi)
__device__ __forceinline__ uint32_t pack_split(float x0, float x1, uint32_t& lo) {
    uint32_t hi;
    asm("cvt.rn.bf16x2.f32 %0, %1, %2;" : "=r"(hi) : "f"(x1), "f"(x0));
    float h0 = __uint_as_float(hi << 16);
    float h1 = __uint_as_float(hi & 0xFFFF0000u);
    float l0 = x0 - h0, l1 = x1 - h1;
    asm("cvt.rn.bf16x2.f32 %0, %1, %2;" : "=r"(lo) : "f"(l1), "f"(l0));
    return hi;
}

// m16n8k16 bf16 MMA (sm_80+ generic PTX)
__device__ __forceinline__ void mma16(float* d, const uint32_t* a, uint32_t b0, uint32_t b1) {
    asm volatile(
        "mma.sync.aligned.m16n8k16.row.col.f32.bf16.bf16.f32 "
        "{%0,%1,%2,%3}, {%4,%5,%6,%7}, {%8,%9}, {%0,%1,%2,%3};"
        : "+f"(d[0]), "+f"(d[1]), "+f"(d[2]), "+f"(d[3])
        : "r"(a[0]), "r"(a[1]), "r"(a[2]), "r"(a[3]), "r"(b0), "r"(b1));
}

// bf16x3 against interleaved fragments
__device__ __forceinline__ void mma_x3(float* d, const uint32_t* ah, const uint32_t* al,
                                       uint2 w0, uint2 w1) {
    mma16(d, al, w0.x, w1.x);   // lo_A * hi_B (small terms first)
    mma16(d, ah, w0.y, w1.y);   // hi_A * lo_B
    mma16(d, ah, w0.x, w1.x);   // hi_A * hi_B
}

// ------------------------- CSR build -----------------------------------------
__global__ void k_hist(const int* __restrict__ ei) {
    int e = blockIdx.x * blockDim.x + threadIdx.x;
    if (e < N_EDGES) atomicAdd(&g_cnt[ei[N_EDGES + e]], 1);
}

__global__ void k_scan() {
    __shared__ int sh[1024];
    __shared__ int base;
    int tid = threadIdx.x;
    if (tid == 0) { base = 0; g_rowptr[0] = 0; }
    __syncthreads();
    for (int start = 0; start < N_NODES; start += 1024) {
        int i = start + tid;
        int v = (i < N_NODES) ? g_cnt[i] : 0;
        sh[tid] = v;
        __syncthreads();
        for (int off = 1; off < 1024; off <<= 1) {
            int t = (tid >= off) ? sh[tid - off] : 0;
            __syncthreads();
            sh[tid] += t;
            __syncthreads();
        }
        if (i < N_NODES) g_rowptr[i + 1] = base + sh[tid];
        __syncthreads();
        if (tid == 1023) base += sh[1023];
        __syncthreads();
    }
    for (int i = tid; i < N_NODES; i += 1024) { g_cnt[i] = 0; g_fill[i] = 0; }
}

__global__ void k_scatter(const int* __restrict__ ei) {
    int e = blockIdx.x * blockDim.x + threadIdx.x;
    if (e >= N_EDGES) return;
    int d = ei[N_EDGES + e];
    int p = atomicAdd(&g_fill[d], 1);
    g_col[g_rowptr[d] + p] = ei[e];
}

// ------------------- weight pre-split kernels ---------------------------------
// Destinations referenced in DEVICE code only (GB300/ATS host-shadow trap).
__global__ void k_prep_ws1(const float* __restrict__ Wl1, const float* __restrict__ Wr1) {
    int idx = blockIdx.x * blockDim.x + threadIdx.x;   // 64 * 64
    if (idx >= 64 * 64) return;
    int m = idx >> 6, c = idx & 63;
    int k0 = 2 * c;
    float v0 = (k0 < 64) ? Wl1[k0 * 64 + m] : Wr1[(k0 - 64) * 64 + m];
    float v1 = (k0 + 1 < 64) ? Wl1[(k0 + 1) * 64 + m] : Wr1[(k0 - 63) * 64 + m];
    uint32_t lo, hi = pack_split(v0, v1, lo);
    g_ws1p[((m >> 3) * 64 + c) * 8 + (m & 7)] = make_uint2(hi, lo);
}

// combined [Wih (K 0..63) | Whh (K 64..191)], 384 rows, K2=96
__global__ void k_prep_wg(const float* __restrict__ Wih, const float* __restrict__ Whh) {
    int idx = blockIdx.x * blockDim.x + threadIdx.x;   // 384 * 96
    if (idx >= G3 * 96) return;
    int row = idx / 96, c = idx % 96;
    int k0 = 2 * c, k1 = 2 * c + 1;                    // pairs never straddle k=64
    float v0 = (k0 < 64) ? Wih[row * 64 + k0] : Whh[row * 128 + k0 - 64];
    float v1 = (k1 < 64) ? Wih[row * 64 + k1] : Whh[row * 128 + k1 - 64];
    uint32_t lo, hi = pack_split(v0, v1, lo);
    g_wgp[((row >> 3) * 96 + c) * 8 + (row & 7)] = make_uint2(hi, lo);
}

// ------------------- layer 0 (batched): agg + SAGE + LN + relu ----------------
__global__ void k_stack0_all(const float* __restrict__ x_seq,
                             const float* __restrict__ Wl, const float* __restrict__ Wr,
                             const float* __restrict__ b0,
                             const float* __restrict__ g, const float* __restrict__ beta) {
    int t = blockIdx.y;
    int n = blockIdx.x * 8 + (threadIdx.x >> 5);
    int lane = threadIdx.x & 31;
    if (n >= N_NODES) return;
    const float* xt = x_seq + t * N_NODES;
    int beg = g_rowptr[n], end = g_rowptr[n + 1];
    float acc = 0.f;
    for (int i = beg + lane; i < end; i += 32) acc += xt[g_col[i]];
    acc = warp_sum(acc);
    float deg = fmaxf((float)(end - beg), 1.f);
    float agg = acc / deg;
    float xv = xt[n];
    float v0 = agg * Wl[lane]      + xv * Wr[lane]      + b0[lane];
    float v1 = agg * Wl[lane + 32] + xv * Wr[lane + 32] + b0[lane + 32];
    float mu = warp_sum(v0 + v1) * (1.f / 64.f);
    float d0 = v0 - mu, d1 = v1 - mu;
    float var = warp_sum(d0 * d0 + d1 * d1) * (1.f / 64.f);
    float inv = rsqrtf(var + LN_EPS);
    float h0a = fmaxf(d0 * inv * g[lane]      + beta[lane], 0.f);
    float h0b = fmaxf(d1 * inv * g[lane + 32] + beta[lane + 32], 0.f);
    size_t row = (size_t)t * N_NODES + n;
    g_h0_all[row * HG + lane]      = h0a;
    g_h0_all[row * HG + lane + 32] = h0b;
    g_ins_all[row * 128 + 64 + lane]      = h0a;
    g_ins_all[row * 128 + 64 + lane + 32] = h0b;
}

// ------------------- layer 1 aggregate (batched, 2-way unrolled) --------------
__global__ void k_agg1_all() {
    int t = blockIdx.y;
    int n = blockIdx.x * 8 + (threadIdx.x >> 5);
    int lane = threadIdx.x & 31;
    if (n >= N_NODES) return;
    const float* h0t = g_h0_all + (size_t)t * N_NODES * HG;
    int beg = g_rowptr[n], end = g_rowptr[n + 1];
    float a0 = 0.f, a1 = 0.f, c0 = 0.f, c1 = 0.f;
    int i = beg;
    for (; i + 1 < end; i += 2) {
        int s0 = g_col[i], s1 = g_col[i + 1];
        a0 += h0t[s0 * HG + lane];
        a1 += h0t[s0 * HG + lane + 32];
        c0 += h0t[s1 * HG + lane];
        c1 += h0t[s1 * HG + lane + 32];
    }
    if (i < end) {
        int s = g_col[i];
        a0 += h0t[s * HG + lane];
        a1 += h0t[s * HG + lane + 32];
    }
    a0 += c0; a1 += c1;
    float inv = 1.f / fmaxf((float)(end - beg), 1.f);
    size_t row = (size_t)t * N_NODES + n;
    g_ins_all[row * 128 + lane]      = a0 * inv;
    g_ins_all[row * 128 + lane + 32] = a1 * inv;
}

// ===================== sage1 bf16x3 GEMM =======================================
// S = ins_all(NTx128) @ ws1^T(64x128) + b1; LN + relu -> g_H_all
__global__ void __launch_bounds__(256)
k_sage(const float* __restrict__ bias, const float* __restrict__ p0,
       const float* __restrict__ p1) {
    constexpr int K2  = 64;
    constexpr int LDK = 68;
    constexpr int BM  = 128;

    extern __shared__ uint32_t smu[];
    uint32_t* Ah = smu;
    uint32_t* Al = smu + BM * LDK;
    float*    S  = (float*)smu;                 // aliases Ah after MMAs

    int tid = threadIdx.x;
    size_t rowBase = (size_t)blockIdx.x * BM;

    for (int idx = tid; idx < BM * 32; idx += 256) {
        int r = idx >> 5, c4 = idx & 31;
        float4 v = *(const float4*)(g_ins_all + (rowBase + r) * 128 + c4 * 4);
        uint32_t lo0, lo1;
        uint32_t hi0 = pack_split(v.x, v.y, lo0);
        uint32_t hi1 = pack_split(v.z, v.w, lo1);
        int j = r * LDK + c4 * 2;
        Ah[j] = hi0; Ah[j + 1] = hi1;
        Al[j] = lo0; Al[j + 1] = lo1;
    }
    __syncthreads();

    int warp = tid >> 5, lane = tid & 31;
    int wm = warp >> 1, wn = warp & 1;          // 4 x 2 warps, WM=32, WN=32
    int g = lane >> 2, tg = lane & 3;
    int m0 = wm * 32, n0 = wn * 32;

    float acc[2][4][4] = {};
#pragma unroll
    for (int kk = 0; kk < K2; kk += 8) {
        uint32_t ah[2][4], al[2][4];
#pragma unroll
        for (int mf = 0; mf < 2; mf++) {
            int base = (m0 + 16 * mf + g) * LDK + kk + tg;
            ah[mf][0] = Ah[base];               al[mf][0] = Al[base];
            ah[mf][1] = Ah[base + 8 * LDK];     al[mf][1] = Al[base + 8 * LDK];
            ah[mf][2] = Ah[base + 4];           al[mf][2] = Al[base + 4];
            ah[mf][3] = Ah[base + 8 * LDK + 4]; al[mf][3] = Al[base + 8 * LDK + 4];
        }
#pragma unroll
        for (int nf = 0; nf < 4; nf++) {
            int fo = (((n0 + 8 * nf) >> 3) * K2 + kk + tg) * 8 + g;
            uint2 w0 = g_ws1p[fo], w1 = g_ws1p[fo + 32];
#pragma unroll
            for (int mf = 0; mf < 2; mf++)
                mma_x3(acc[mf][nf], ah[mf], al[mf], w0, w1);
        }
    }

    __syncthreads();
#pragma unroll
    for (int mf = 0; mf < 2; mf++)
#pragma unroll
        for (int nf = 0; nf < 4; nf++) {
            int r = m0 + 16 * mf + g;
            int c = n0 + 8 * nf + 2 * tg;
            S[r * 68 + c]           = acc[mf][nf][0] + bias[c];
            S[r * 68 + c + 1]       = acc[mf][nf][1] + bias[c + 1];
            S[(r + 8) * 68 + c]     = acc[mf][nf][2] + bias[c];
            S[(r + 8) * 68 + c + 1] = acc[mf][nf][3] + bias[c + 1];
        }
    __syncthreads();
#pragma unroll
    for (int i = 0; i < 16; i++) {
        int r = warp * 16 + i;
        float v0 = S[r * 68 + lane];
        float v1 = S[r * 68 + lane + 32];
        float mu = warp_sum(v0 + v1) * (1.f / 64.f);
        float d0 = v0 - mu, d1 = v1 - mu;
        float var = warp_sum(d0 * d0 + d1 * d1) * (1.f / 64.f);
        float inv = rsqrtf(var + LN_EPS);
        size_t rowg = rowBase + r;
        g_H_all[rowg * HG + lane]      = fmaxf(d0 * inv * p0[lane]      + p1[lane], 0.f);
        g_H_all[rowg * HG + lane + 32] = fmaxf(d1 * inv * p0[lane + 32] + p1[lane + 32], 0.f);
    }
}

// ===================== persistent GRU chain (gi fused) =========================
// One launch. CTA owns 32 nodes; loops t=0..15 with h resident in smem.
// Per step: A = [H_t (K 0..63) | h (K 64..191)] staged+split in smem;
// bf16x3 MMA vs combined pre-split [Wih|Whh] (L2-resident); n-gate uses
// k-range-split accumulators (inn: kk<32, hn: kk>=32). Gates fully in-register.
__global__ void __launch_bounds__(256, 2)
k_chain(const float* __restrict__ bih, const float* __restrict__ bhh,
        const float* __restrict__ headW, const float* __restrict__ headb,
        float* __restrict__ y) {
    constexpr int K2  = 96;
    constexpr int LDK = 100;                    // %32==4 -> conflict-free
    constexpr int BM  = 32;                     // 20000 = 625 * 32 exactly

    __shared__ float    hs[BM][HT + 4];
    __shared__ uint32_t Ah[BM * LDK];
    __shared__ uint32_t Al[BM * LDK];

    int tid = threadIdx.x, warp = tid >> 5, lane = tid & 31;
    int nodeBase = blockIdx.x * BM;
    int g = lane >> 2, tg = lane & 3;
    int n0 = warp * 16;                         // 8 warps x WN=16 over 128 cols

    for (int i = tid; i < BM * HT; i += 256) hs[i >> 7][i & 127] = 0.f;
    __syncthreads();

    for (int t = 0; t < T_STEPS; t++) {
        const float* Ht = g_H_all + ((size_t)t * N_NODES + nodeBase) * HG;
        // ---- L2 prefetch of next step's H slice (8KB = 64 lines) ----
        if (t + 1 < T_STEPS && tid < 64) {
            const char* gp = (const char*)(g_H_all + ((size_t)(t + 1) * N_NODES + nodeBase) * HG);
            asm volatile("prefetch.global.L2 [%0];" :: "l"(gp + (size_t)tid * 128));
        }
        // ---- stage A: [H_t | h] -> packed bf16 hi/lo ----
        for (int i = tid; i < BM * 48; i += 256) {
            int r = i / 48, q = i % 48;         // q: float4 index over 192 floats
            float4 v = (q < 16) ? *(const float4*)(Ht + (size_t)r * HG + q * 4)
                                : *(const float4*)(&hs[r][(q - 16) * 4]);
            uint32_t lo0, lo1;
            uint32_t hi0 = pack_split(v.x, v.y, lo0);
            uint32_t hi1 = pack_split(v.z, v.w, lo1);
            int j = r * LDK + q * 2;
            Ah[j] = hi0; Ah[j + 1] = hi1;
            Al[j] = lo0; Al[j + 1] = lo1;
        }
        __syncthreads();

        float acc[4][2][2][4] = {};             // [r,z,n_i,n_h][MF][NF][4]
#pragma unroll
        for (int kk = 0; kk < K2; kk += 8) {
            uint32_t ah[2][4], al[2][4];
#pragma unroll
            for (int mf = 0; mf < 2; mf++) {
                int base = (16 * mf + g) * LDK + kk + tg;
                ah[mf][0] = Ah[base];               al[mf][0] = Al[base];
                ah[mf][1] = Ah[base + 8 * LDK];     al[mf][1] = Al[base + 8 * LDK];
                ah[mf][2] = Ah[base + 4];           al[mf][2] = Al[base + 4];
                ah[mf][3] = Ah[base + 8 * LDK + 4]; al[mf][3] = Al[base + 8 * LDK + 4];
            }
#pragma unroll
            for (int gt = 0; gt < 3; gt++) {
                int at = (gt < 2) ? gt : ((kk < 32) ? 2 : 3);
#pragma unroll
                for (int nf = 0; nf < 2; nf++) {
                    int nrow = gt * HT + n0 + 8 * nf;
                    int fo = ((nrow >> 3) * K2 + kk + tg) * 8 + g;
                    uint2 w0 = g_wgp[fo], w1 = g_wgp[fo + 32];
#pragma unroll
                    for (int mf = 0; mf < 2; mf++)
                        mma_x3(acc[at][mf][nf], ah[mf], al[mf], w0, w1);
                }
            }
        }

        // ---- gates epilogue: fully in-register ----
#pragma unroll
        for (int mf = 0; mf < 2; mf++)
#pragma unroll
            for (int nf = 0; nf < 2; nf++)
#pragma unroll
                for (int half = 0; half < 2; half++) {
                    int nl = 16 * mf + g + 8 * half;
                    int c = n0 + 8 * nf + 2 * tg;
                    int h2 = half * 2;
                    float r0 = 1.f / (1.f + __expf(-(acc[0][mf][nf][h2]     + bih[c]     + bhh[c])));
                    float r1 = 1.f / (1.f + __expf(-(acc[0][mf][nf][h2 + 1] + bih[c + 1] + bhh[c + 1])));
                    float z0 = 1.f / (1.f + __expf(-(acc[1][mf][nf][h2]     + bih[128 + c]     + bhh[128 + c])));
                    float z1 = 1.f / (1.f + __expf(-(acc[1][mf][nf][h2 + 1] + bih[128 + c + 1] + bhh[128 + c + 1])));
                    float n0v = tanhf(acc[2][mf][nf][h2]     + bih[256 + c]     +
                                      r0 * (acc[3][mf][nf][h2]     + bhh[256 + c]));
                    float n1v = tanhf(acc[2][mf][nf][h2 + 1] + bih[256 + c + 1] +
                                      r1 * (acc[3][mf][nf][h2 + 1] + bhh[256 + c + 1]));
                    float hx = hs[nl][c], hy = hs[nl][c + 1];
                    hs[nl][c]     = (1.f - z0) * n0v + z0 * hx;
                    hs[nl][c + 1] = (1.f - z1) * n1v + z1 * hy;
                }
        __syncthreads();
    }

    // ---- fused head: y[node] = dot(h, headW) + headb ----
#pragma unroll
    for (int i = 0; i < 4; i++) {
        int r = warp * 4 + i;
        float acc = 0.f;
#pragma unroll
        for (int q = 0; q < 4; q++) {
            int j = lane + 32 * q;
            acc += hs[r][j] * headW[j];
        }
        acc = warp_sum(acc);
        if (lane == 0) y[nodeBase + r] = acc + headb[0];
    }
}

// ------------------------- launch ------------------------------------------------
extern "C" void kernel_launch(void* const* d_in, const int* in_sizes, int n_in,
                              void* d_out, int out_size) {
    const float* x_seq = (const float*)d_in[0];
    const int*   ei    = (const int*)d_in[1];
    const float* W_l0  = (const float*)d_in[2];
    const float* W_r0  = (const float*)d_in[3];
    const float* b0    = (const float*)d_in[4];
    const float* ln0g  = (const float*)d_in[5];
    const float* ln0b  = (const float*)d_in[6];
    const float* W_l1  = (const float*)d_in[7];
    const float* W_r1  = (const float*)d_in[8];
    const float* b1    = (const float*)d_in[9];
    const float* ln1g  = (const float*)d_in[10];
    const float* ln1b  = (const float*)d_in[11];
    const float* Wih   = (const float*)d_in[12];
    const float* Whh   = (const float*)d_in[13];
    const float* bih   = (const float*)d_in[14];
    const float* bhh   = (const float*)d_in[15];
    const float* headW = (const float*)d_in[16];
    const float* headb = (const float*)d_in[17];
    float* y = (float*)d_out;

    const int SMEM_S = 128 * 68 * 2 * 4;   // 69632
    cudaFuncSetAttribute(k_sage, cudaFuncAttributeMaxDynamicSharedMemorySize, SMEM_S);

    // CSR build (k_scan re-zeroes cnt/fill for graph replays)
    k_hist<<<(N_EDGES + 255) / 256, 256>>>(ei);
    k_scan<<<1, 1024>>>();
    k_scatter<<<(N_EDGES + 255) / 256, 256>>>(ei);

    // phase A (all timesteps in parallel)
    dim3 gridA((N_NODES + 7) / 8, T_STEPS);
    k_stack0_all<<<gridA, 256>>>(x_seq, W_l0, W_r0, b0, ln0g, ln0b);
    k_prep_ws1<<<(64 * 64 + 255) / 256, 256>>>(W_l1, W_r1);
    k_prep_wg<<<(G3 * 96 + 255) / 256, 256>>>(Wih, Whh);
    k_agg1_all<<<gridA, 256>>>();

    k_sage<<<NT / 128, 256, SMEM_S>>>(b1, ln1g, ln1b);

    // phase B: single persistent-chain launch (gi GEMM + GRU + head fused)
    k_chain<<<N_NODES / 32, 256>>>(bih, bhh, headW, headb, y);
}